// round 2
// baseline (speedup 1.0000x reference)
#include <cuda_runtime.h>
#include <math.h>

// ---------------- dimensions ----------------
#define NB 8          // batch*groups
#define S  66
#define S2 4356       // 66*66
#define S3 287496     // 66^3
#define HH 33
#define H2 1089       // 33*33
#define H3 35937      // 33^3
#define D3 262144     // 64^3

// output packing offsets (x, helmholtz, vel, vel_phi, vel_vort)
#define OFF_X     0
#define OFF_HELM  16777216
#define OFF_VEL   25977088
#define OFF_VPHI  32268544
#define OFF_VVORT 38560000

// ---------------- scratch (static device memory; no allocation APIs) ----------------
__device__ float g_f[3][NB*64*H3];     // encoder outputs: pm, pb, nm
__device__ float g_corr[NB*54*H3];     // correlation output
__device__ float g_c1[NB*16*H3];       // conv1 raw out (phi 0-7, vort 8-15)
__device__ float g_u1[NB*16*S3];       // upsampled (post BN1+relu)
__device__ float g_c2[NB*16*S3];       // conv2 raw out
__device__ float g_phi1[64*D3];        // advect pass 1
__device__ float g_comb[64*D3];        // 1.5*tex - 0.5*phi2
__device__ float g_pred[64*D3];        // final advect result
__device__ float g_gbuf[64*D3];        // FF hidden
__device__ float g_wp1[54*27*16];      // packed conv1 weights [(ic*27+tap)*16+oc]
__device__ float g_wp2[27*8*16];       // packed conv2 weights [(tap*8+icg)*16+oc]
__device__ float g_stat[64];           // mean1[16], istd1[16], mean2[16], istd2[16]
__device__ double g_part[16*32*2];     // partial reduction sums

// ---------------- weight packing ----------------
__global__ void pack_kernel(const float* __restrict__ pw1, const float* __restrict__ vw1,
                            const float* __restrict__ pw2, const float* __restrict__ vw2) {
    int i = blockIdx.x * blockDim.x + threadIdx.x;
    if (i < 54*27*16) {
        int oc = i & 15; int t = (i >> 4) % 27; int ic = (i >> 4) / 27;
        g_wp1[i] = (oc < 8) ? pw1[(oc*54 + ic)*27 + t] : vw1[((oc-8)*54 + ic)*27 + t];
    }
    if (i < 27*8*16) {
        int oc = i & 15; int icg = (i >> 4) % 8; int t = (i >> 4) / 8;
        g_wp2[i] = (oc < 8) ? pw2[(oc*8 + icg)*27 + t] : vw2[((oc-8)*8 + icg)*27 + t];
    }
}

// ---------------- encoder: conv3d stride 2, kernel 2, input = src*mul ----------------
__global__ void enc_kernel(const float* __restrict__ src, const float* __restrict__ mul,
                           const float* __restrict__ w, const float* __restrict__ b, int variant) {
    int idx = blockIdx.x * blockDim.x + threadIdx.x;
    if (idx >= NB*64*H3) return;
    int p = idx % H3;
    int o = (idx / H3) % 64;
    int n = idx / (64*H3);
    int z = p % HH, y = (p / HH) % HH, x = p / H2;
    int X = 2*x, Y = 2*y, Z = 2*z;

    float m[8];
#pragma unroll
    for (int t = 0; t < 8; t++) {
        int dx = t >> 2, dy = (t >> 1) & 1, dz = t & 1;
        m[t] = mul[((X+dx)*S + (Y+dy))*S + (Z+dz)];
    }
    float acc = b[o];
    const float* wo = w + o*64;
#pragma unroll
    for (int i = 0; i < 8; i++) {
        int base = (n*8 + i)*S3 + (X*S + Y)*S + Z;
#pragma unroll
        for (int t = 0; t < 8; t++) {
            int dx = t >> 2, dy = (t >> 1) & 1, dz = t & 1;
            acc += src[base + (dx*S + dy)*S + dz] * m[t] * wo[i*8 + t];
        }
    }
    g_f[variant][idx] = acc;
}

// ---------------- correlation: 2x27 channels ----------------
__global__ void corr_kernel() {
    int idx = blockIdx.x * blockDim.x + threadIdx.x;
    if (idx >= NB*H3) return;
    int p = idx % H3; int n = idx / H3;
    int z = p % HH, y = (p / HH) % HH, x = p / H2;

    const float* A0 = &g_f[0][n*64*H3 + p];
    const float* A1 = &g_f[1][n*64*H3 + p];
    const float* B  = &g_f[2][n*64*H3 + p];

    int off[9]; bool ok[9];
    {
        int s = 0;
        for (int di = -1; di <= 1; di++)
            for (int dj = -1; dj <= 1; dj++) {
                ok[s] = (x+di >= 0 && x+di < HH && y+dj >= 0 && y+dj < HH);
                off[s] = (di*HH + dj)*HH;
                s++;
            }
    }
    float acc[18];
#pragma unroll
    for (int s = 0; s < 18; s++) acc[s] = 0.f;

    for (int c = 0; c < 64; c++) {
        float a0 = A0[c*H3];
        float a1 = A1[c*H3];
        const float* Bc = B + c*H3;
#pragma unroll
        for (int s = 0; s < 9; s++) {
            float bv = ok[s] ? Bc[off[s]] : 0.f;
            acc[s]   += a0 * bv;
            acc[9+s] += a1 * bv;
        }
    }
    float zm0 = (z == HH-1) ? 0.f : 1.f;   // pm[0] zeroes last z slab
    float zm2 = (z == 0)    ? 0.f : 1.f;   // pm[2] zeroes first z slab
    for (int w = 0; w < 2; w++)
        for (int s = 0; s < 9; s++) {
            float d = acc[w*9 + s] * (1.f/64.f);
            g_corr[(n*54 + w*27 +      s)*H3 + p] = d * zm0;
            g_corr[(n*54 + w*27 +  9 + s)*H3 + p] = d;
            g_corr[(n*54 + w*27 + 18 + s)*H3 + p] = d * zm2;
        }
}

// ---------------- conv1: 54 -> 16, 3^3, pad 1, on 33^3 ----------------
__global__ void conv1_kernel() {
    extern __shared__ float ws[];
    for (int i = threadIdx.x; i < 54*27*16; i += blockDim.x) ws[i] = g_wp1[i];
    __syncthreads();

    int idx = blockIdx.x * blockDim.x + threadIdx.x;
    if (idx >= NB*H3) return;
    int p = idx % H3; int n = idx / H3;
    int z = p % HH, y = (p / HH) % HH, x = p / H2;

    float acc[16];
#pragma unroll
    for (int i = 0; i < 16; i++) acc[i] = 0.f;

    const float* cbase = g_corr + n*54*H3;
    for (int tap = 0; tap < 27; tap++) {
        int dx = tap/9 - 1, dy = (tap/3)%3 - 1, dz = tap%3 - 1;
        int xx = x+dx, yy = y+dy, zz = z+dz;
        if ((unsigned)xx >= (unsigned)HH || (unsigned)yy >= (unsigned)HH || (unsigned)zz >= (unsigned)HH) continue;
        int q = (xx*HH + yy)*HH + zz;
        for (int ic = 0; ic < 54; ic++) {
            float v = cbase[ic*H3 + q];
            const float4* wv = reinterpret_cast<const float4*>(ws + ((ic*27 + tap) << 4));
            float4 w0 = wv[0], w1 = wv[1], w2 = wv[2], w3 = wv[3];
            acc[0]  += v*w0.x; acc[1]  += v*w0.y; acc[2]  += v*w0.z; acc[3]  += v*w0.w;
            acc[4]  += v*w1.x; acc[5]  += v*w1.y; acc[6]  += v*w1.z; acc[7]  += v*w1.w;
            acc[8]  += v*w2.x; acc[9]  += v*w2.y; acc[10] += v*w2.z; acc[11] += v*w2.w;
            acc[12] += v*w3.x; acc[13] += v*w3.y; acc[14] += v*w3.z; acc[15] += v*w3.w;
        }
    }
#pragma unroll
    for (int oc = 0; oc < 16; oc++) g_c1[(n*16 + oc)*H3 + p] = acc[oc];
}

// ---------------- BN stats (two-stage deterministic) ----------------
__global__ void bn_stats_partial(int phase) {
    const float* src = phase ? g_c2 : g_c1;
    int spatial = phase ? S3 : H3;
    int total = NB * spatial;
    int ch = blockIdx.x, sl = blockIdx.y;
    double s = 0.0, s2 = 0.0;
    for (int i = sl*blockDim.x + threadIdx.x; i < total; i += 32*blockDim.x) {
        int n = i / spatial, p = i % spatial;
        float v = src[(n*16 + ch)*spatial + p];
        s += v; s2 += (double)v * v;
    }
    __shared__ double sh[512], sh2[512];
    sh[threadIdx.x] = s; sh2[threadIdx.x] = s2;
    __syncthreads();
    for (int st = 256; st > 0; st >>= 1) {
        if (threadIdx.x < st) { sh[threadIdx.x] += sh[threadIdx.x+st]; sh2[threadIdx.x] += sh2[threadIdx.x+st]; }
        __syncthreads();
    }
    if (threadIdx.x == 0) {
        g_part[(ch*32 + sl)*2 + 0] = sh[0];
        g_part[(ch*32 + sl)*2 + 1] = sh2[0];
    }
}

__global__ void bn_stats_final(int phase) {
    int ch = blockIdx.x;
    if (threadIdx.x != 0) return;
    int spatial = phase ? S3 : H3;
    double total = (double)NB * spatial;
    double s = 0.0, s2 = 0.0;
    for (int i = 0; i < 32; i++) { s += g_part[(ch*32+i)*2]; s2 += g_part[(ch*32+i)*2+1]; }
    double mean = s / total;
    double var = s2 / total - mean*mean;
    g_stat[phase*32 + ch]      = (float)mean;
    g_stat[phase*32 + 16 + ch] = (float)(1.0 / sqrt(var + 1e-5));
}

// ---------------- BN1 + relu + trilinear upsample x2 (align_corners) ----------------
__device__ __forceinline__ float bnrelu(float v, float sc, float sh) { return fmaxf(v*sc + sh, 0.f); }

__global__ void upsample_kernel(const float* __restrict__ g1p, const float* __restrict__ b1p,
                                const float* __restrict__ g1v, const float* __restrict__ b1v) {
    int idx = blockIdx.x * blockDim.x + threadIdx.x;
    if (idx >= NB*16*S3) return;
    int p = idx % S3; int ch = (idx / S3) % 16; int n = idx / (16*S3);
    int Z = p % S, Y = (p / S) % S, X = p / S2;

    float mean = g_stat[ch], istd = g_stat[16 + ch];
    float gg = (ch < 8) ? g1p[ch] : g1v[ch-8];
    float bb = (ch < 8) ? b1p[ch] : b1v[ch-8];
    float sc = istd * gg, sh = bb - mean * sc;

    const float SC = 32.f / 65.f;
    float sx = X * SC; int x0 = (int)sx; float fx = sx - x0; int x1 = min(x0+1, 32);
    float sy = Y * SC; int y0 = (int)sy; float fy = sy - y0; int y1 = min(y0+1, 32);
    float sz = Z * SC; int z0 = (int)sz; float fz = sz - z0; int z1 = min(z0+1, 32);

    const float* base = g_c1 + (n*16 + ch)*H3;
#define RD(xi,yi,zi) bnrelu(base[((xi)*HH+(yi))*HH+(zi)], sc, sh)
    float v =
      ((RD(x0,y0,z0)*(1-fx) + RD(x1,y0,z0)*fx)*(1-fy) + (RD(x0,y1,z0)*(1-fx) + RD(x1,y1,z0)*fx)*fy)*(1-fz)
    + ((RD(x0,y0,z1)*(1-fx) + RD(x1,y0,z1)*fx)*(1-fy) + (RD(x0,y1,z1)*(1-fx) + RD(x1,y1,z1)*fx)*fy)*fz;
#undef RD
    g_u1[idx] = v;
}

// ---------------- conv2: grouped 2x(8->8), 3^3, pad 1, on 66^3 ----------------
__global__ void conv2_kernel() {
    __shared__ float ws[27*8*16];
    for (int i = threadIdx.x; i < 27*8*16; i += blockDim.x) ws[i] = g_wp2[i];
    __syncthreads();

    int idx = blockIdx.x * blockDim.x + threadIdx.x;
    if (idx >= NB*S3) return;
    int p = idx % S3; int n = idx / S3;
    int z = p % S, y = (p / S) % S, x = p / S2;

    float acc[16];
#pragma unroll
    for (int i = 0; i < 16; i++) acc[i] = 0.f;

    const float* ubase = g_u1 + n*16*S3;
    for (int tap = 0; tap < 27; tap++) {
        int dx = tap/9 - 1, dy = (tap/3)%3 - 1, dz = tap%3 - 1;
        int xx = x+dx, yy = y+dy, zz = z+dz;
        if ((unsigned)xx >= (unsigned)S || (unsigned)yy >= (unsigned)S || (unsigned)zz >= (unsigned)S) continue;
        int q = (xx*S + yy)*S + zz;
#pragma unroll
        for (int icg = 0; icg < 8; icg++) {
            float vp = ubase[icg*S3 + q];
            float vv = ubase[(8+icg)*S3 + q];
            const float4* wv = reinterpret_cast<const float4*>(ws + ((tap*8 + icg) << 4));
            float4 w0 = wv[0], w1 = wv[1], w2 = wv[2], w3 = wv[3];
            acc[0]  += vp*w0.x; acc[1]  += vp*w0.y; acc[2]  += vp*w0.z; acc[3]  += vp*w0.w;
            acc[4]  += vp*w1.x; acc[5]  += vp*w1.y; acc[6]  += vp*w1.z; acc[7]  += vp*w1.w;
            acc[8]  += vv*w2.x; acc[9]  += vv*w2.y; acc[10] += vv*w2.z; acc[11] += vv*w2.w;
            acc[12] += vv*w3.x; acc[13] += vv*w3.y; acc[14] += vv*w3.z; acc[15] += vv*w3.w;
        }
    }
#pragma unroll
    for (int oc = 0; oc < 16; oc++) g_c2[(n*16 + oc)*S3 + p] = acc[oc];
}

// ---------------- BN2 + relu + 1x1 heads -> helmholtz (into d_out) ----------------
__global__ void helm_kernel(const float* __restrict__ g2p, const float* __restrict__ b2p,
                            const float* __restrict__ g2v, const float* __restrict__ b2v,
                            const float* __restrict__ pow_, const float* __restrict__ pob,
                            const float* __restrict__ vow,  const float* __restrict__ vob,
                            const float* __restrict__ phiw, const float* __restrict__ vortw,
                            float* __restrict__ out) {
    int idx = blockIdx.x * blockDim.x + threadIdx.x;
    if (idx >= NB*S3) return;
    int p = idx % S3; int n = idx / S3;

    float y[16];
#pragma unroll
    for (int c = 0; c < 16; c++) {
        float mean = g_stat[32 + c], istd = g_stat[48 + c];
        float gg = (c < 8) ? g2p[c] : g2v[c-8];
        float bb = (c < 8) ? b2p[c] : b2v[c-8];
        float v = (g_c2[(n*16 + c)*S3 + p] - mean) * istd * gg + bb;
        y[c] = fmaxf(v, 0.f);
    }
    float ph = pob[0];
#pragma unroll
    for (int c = 0; c < 8; c++) ph += y[c] * pow_[c];
    ph *= phiw[0];
    out[OFF_HELM + (n*4)*S3 + p] = ph;
    float vscale = vortw[0] * 66.f;
#pragma unroll
    for (int r = 0; r < 3; r++) {
        float v = vob[r];
#pragma unroll
        for (int c = 0; c < 8; c++) v += y[8+c] * vow[r*8 + c];
        out[OFF_HELM + (n*4 + 1 + r)*S3 + p] = v * vscale;
    }
}

// ---------------- velocity stencils (into d_out) ----------------
__device__ __forceinline__ float HV(const float* hm, int ch, int x, int y, int z) {
    return hm[ch*S3 + (x*S + y)*S + z];
}

__global__ void vel_kernel(float* __restrict__ out) {
    int idx = blockIdx.x * blockDim.x + threadIdx.x;
    if (idx >= NB*D3) return;
    int p = idx % D3; int n = idx / D3;
    int k = p & 63, j = (p >> 6) & 63, i = p >> 12;
    const float* hm = out + OFF_HELM + n*4*S3;

    // vel_phi
    float vp0 = 0.5f * (HV(hm,0, 1+i, 1+j, k+2) - HV(hm,0, 1+i, 1+j, k));
    float vp1 = 0.5f * (HV(hm,0, 1+i, j+2, 1+k) - HV(hm,0, 1+i, j,   1+k));
    float vp2 = 0.5f * (HV(hm,0, i+2, 1+j, 1+k) - HV(hm,0, i,   1+j, 1+k));

    // vel_vort (s0=ch1, s1=ch2, s2=ch3)
    float ua = (HV(hm,2, 2+i,1+j,k+1) - HV(hm,2, 1+i,1+j,k+1)) - (HV(hm,1, 1+i,2+j,k+1) - HV(hm,1, 1+i,1+j,k+1));
    float ub = (HV(hm,2, 2+i,1+j,k  ) - HV(hm,2, 1+i,1+j,k  )) - (HV(hm,1, 1+i,2+j,k  ) - HV(hm,1, 1+i,1+j,k  ));
    float vv0 = 0.5f * (ua + ub);
    float va = (HV(hm,1, 1+i,j+1,k+2) - HV(hm,1, 1+i,j+1,k+1)) - (HV(hm,3, i+2,j+1,k+1) - HV(hm,3, i+1,j+1,k+1));
    float vb = (HV(hm,1, 1+i,j,  k+2) - HV(hm,1, 1+i,j,  k+1)) - (HV(hm,3, i+2,j,  k+1) - HV(hm,3, i+1,j,  k+1));
    float vv1 = 0.5f * (va + vb);
    float wa = (HV(hm,3, i+1,j+2,k+1) - HV(hm,3, i+1,j+1,k+1)) - (HV(hm,2, i+1,j+1,k+2) - HV(hm,2, i+1,j+1,k+1));
    float wb = (HV(hm,3, i,  j+2,k+1) - HV(hm,3, i,  j+1,k+1)) - (HV(hm,2, i,  j+1,k+2) - HV(hm,2, i,  j+1,k+1));
    float vv2 = 0.5f * (wa + wb);

    int b = n*3*D3 + p;
    out[OFF_VPHI  + b        ] = vp0;
    out[OFF_VPHI  + b + D3   ] = vp1;
    out[OFF_VPHI  + b + 2*D3 ] = vp2;
    out[OFF_VVORT + b        ] = vv0;
    out[OFF_VVORT + b + D3   ] = vv1;
    out[OFF_VVORT + b + 2*D3 ] = vv2;
    out[OFF_VEL   + b        ] = vp0 + vv0;
    out[OFF_VEL   + b + D3   ] = vp1 + vv1;
    out[OFF_VEL   + b + 2*D3 ] = vp2 + vv2;
}

// ---------------- BFECC advect passes ----------------
// mode 0: dst=g_phi1,  src=texture,  sgn=+1
// mode 1: dst=g_comb,  src=g_phi1,   sgn=-1, combine: 1.5*tex - 0.5*sample
// mode 2: dst=g_pred,  src=g_comb,   sgn=+1
__global__ void advect_kernel(const float* __restrict__ ext_src, const float* __restrict__ tex,
                              const float* __restrict__ vel, float sgn, int mode) {
    int idx = blockIdx.x * blockDim.x + threadIdx.x;
    if (idx >= NB*D3) return;
    int p = idx % D3; int n = idx / D3;
    int k = p & 63, j = (p >> 6) & 63, i = p >> 12;

    float v0 = vel[(n*3    )*D3 + p];
    float v1 = vel[(n*3 + 1)*D3 + p];
    float v2 = vel[(n*3 + 2)*D3 + p];
    float px = (float)i - sgn*v2;
    float py = (float)j - sgn*v1;
    float pz = (float)k - sgn*v0;
    px = fminf(fmaxf(px, 0.f), 63.f);
    py = fminf(fmaxf(py, 0.f), 63.f);
    pz = fminf(fmaxf(pz, 0.f), 63.f);
    int x0 = (int)px; float fx = px - x0; int x1 = min(x0+1, 63);
    int y0 = (int)py; float fy = py - y0; int y1 = min(y0+1, 63);
    int z0 = (int)pz; float fz = pz - z0; int z1 = min(z0+1, 63);

    float w000 = (1-fx)*(1-fy)*(1-fz), w001 = (1-fx)*(1-fy)*fz;
    float w010 = (1-fx)*fy*(1-fz),     w011 = (1-fx)*fy*fz;
    float w100 = fx*(1-fy)*(1-fz),     w101 = fx*(1-fy)*fz;
    float w110 = fx*fy*(1-fz),         w111 = fx*fy*fz;

    int b00 = (x0*64 + y0)*64, b01 = (x0*64 + y1)*64;
    int b10 = (x1*64 + y0)*64, b11 = (x1*64 + y1)*64;

    const float* src = (mode == 0) ? ext_src : ((mode == 1) ? g_phi1 : g_comb);
    float* dst = (mode == 0) ? g_phi1 : ((mode == 1) ? g_comb : g_pred);

#pragma unroll
    for (int c = 0; c < 8; c++) {
        const float* s = src + (n*8 + c)*D3;
        float v = w000*s[b00+z0] + w001*s[b00+z1] + w010*s[b01+z0] + w011*s[b01+z1]
                + w100*s[b10+z0] + w101*s[b10+z1] + w110*s[b11+z0] + w111*s[b11+z1];
        if (mode == 1) v = 1.5f * tex[(n*8 + c)*D3 + p] - 0.5f * v;
        dst[(n*8 + c)*D3 + p] = v;
    }
}

// ---------------- LN + FF stage 1 (LN, @W1+b1, exact GELU) ----------------
__global__ void f1_kernel(const float* __restrict__ lng, const float* __restrict__ lnb,
                          const float* __restrict__ w1, const float* __restrict__ b1) {
    __shared__ float W[4096], Bv[64], G[64], Bt[64];
    for (int i = threadIdx.x; i < 4096; i += blockDim.x) W[i] = w1[i];
    if (threadIdx.x < 64) { Bv[threadIdx.x] = b1[threadIdx.x]; G[threadIdx.x] = lng[threadIdx.x]; Bt[threadIdx.x] = lnb[threadIdx.x]; }
    __syncthreads();

    int p = blockIdx.x * blockDim.x + threadIdx.x;
    if (p >= D3) return;
    float h[64]; float s = 0.f, s2 = 0.f;
#pragma unroll
    for (int c = 0; c < 64; c++) { float v = g_pred[c*D3 + p]; h[c] = v; s += v; s2 += v*v; }
    float mean = s * (1.f/64.f);
    float var  = s2 * (1.f/64.f) - mean*mean;
    float is = rsqrtf(var + 1e-5f);
#pragma unroll
    for (int c = 0; c < 64; c++) h[c] = (h[c] - mean) * is * G[c] + Bt[c];

    for (int jj = 0; jj < 64; jj++) {
        float a = Bv[jj];
#pragma unroll
        for (int ii = 0; ii < 64; ii++) a += h[ii] * W[ii*64 + jj];
        float g = 0.5f * a * (1.f + erff(a * 0.70710678118f));
        g_gbuf[jj*D3 + p] = g;
    }
}

// ---------------- FF stage 2 (@W2+b2, residual -> d_out x) ----------------
__global__ void f2_kernel(const float* __restrict__ w2, const float* __restrict__ b2,
                          float* __restrict__ out) {
    __shared__ float W[4096], Bv[64];
    for (int i = threadIdx.x; i < 4096; i += blockDim.x) W[i] = w2[i];
    if (threadIdx.x < 64) Bv[threadIdx.x] = b2[threadIdx.x];
    __syncthreads();

    int p = blockIdx.x * blockDim.x + threadIdx.x;
    if (p >= D3) return;
    float g[64];
#pragma unroll
    for (int c = 0; c < 64; c++) g[c] = g_gbuf[c*D3 + p];
    for (int jj = 0; jj < 64; jj++) {
        float a = Bv[jj];
#pragma unroll
        for (int ii = 0; ii < 64; ii++) a += g[ii] * W[ii*64 + jj];
        out[OFF_X + jj*D3 + p] = g_pred[jj*D3 + p] + a;
    }
}

// ---------------- host launch ----------------
extern "C" void kernel_launch(void* const* d_in, const int* in_sizes, int n_in,
                              void* d_out, int out_size) {
    const float* prev      = (const float*)d_in[0];
    const float* nxt       = (const float*)d_in[1];
    const float* texture   = (const float*)d_in[2];
    const float* mask      = (const float*)d_in[3];
    const float* boundary  = (const float*)d_in[4];
    const float* enc_w     = (const float*)d_in[5];
    const float* enc_b     = (const float*)d_in[6];
    const float* phi_c1_w  = (const float*)d_in[7];
    const float* phi_bn1_g = (const float*)d_in[8];
    const float* phi_bn1_b = (const float*)d_in[9];
    const float* phi_c2_w  = (const float*)d_in[10];
    const float* phi_bn2_g = (const float*)d_in[11];
    const float* phi_bn2_b = (const float*)d_in[12];
    const float* phi_out_w = (const float*)d_in[13];
    const float* phi_out_b = (const float*)d_in[14];
    const float* vort_c1_w = (const float*)d_in[15];
    const float* vort_bn1_g= (const float*)d_in[16];
    const float* vort_bn1_b= (const float*)d_in[17];
    const float* vort_c2_w = (const float*)d_in[18];
    const float* vort_bn2_g= (const float*)d_in[19];
    const float* vort_bn2_b= (const float*)d_in[20];
    const float* vort_out_w= (const float*)d_in[21];
    const float* vort_out_b= (const float*)d_in[22];
    const float* phi_weight= (const float*)d_in[23];
    const float* vort_weight=(const float*)d_in[24];
    const float* ln_g      = (const float*)d_in[25];
    const float* ln_b      = (const float*)d_in[26];
    const float* ff_w1     = (const float*)d_in[27];
    const float* ff_b1     = (const float*)d_in[28];
    const float* ff_w2     = (const float*)d_in[29];
    const float* ff_b2     = (const float*)d_in[30];
    float* out = (float*)d_out;

    pack_kernel<<<(54*27*16 + 255)/256, 256>>>(phi_c1_w, vort_c1_w, phi_c2_w, vort_c2_w);

    int encN = NB*64*H3;
    enc_kernel<<<(encN + 255)/256, 256>>>(prev, mask,     enc_w, enc_b, 0);
    enc_kernel<<<(encN + 255)/256, 256>>>(prev, boundary, enc_w, enc_b, 1);
    enc_kernel<<<(encN + 255)/256, 256>>>(nxt,  mask,     enc_w, enc_b, 2);

    corr_kernel<<<(NB*H3 + 255)/256, 256>>>();

    cudaFuncSetAttribute(conv1_kernel, cudaFuncAttributeMaxDynamicSharedMemorySize, 54*27*16*4);
    conv1_kernel<<<(NB*H3 + 255)/256, 256, 54*27*16*4>>>();

    bn_stats_partial<<<dim3(16, 32), 512>>>(0);
    bn_stats_final<<<16, 32>>>(0);

    int upN = NB*16*S3;
    upsample_kernel<<<(upN + 255)/256, 256>>>(phi_bn1_g, phi_bn1_b, vort_bn1_g, vort_bn1_b);

    conv2_kernel<<<(NB*S3 + 255)/256, 256>>>();

    bn_stats_partial<<<dim3(16, 32), 512>>>(1);
    bn_stats_final<<<16, 32>>>(1);

    helm_kernel<<<(NB*S3 + 255)/256, 256>>>(phi_bn2_g, phi_bn2_b, vort_bn2_g, vort_bn2_b,
                                            phi_out_w, phi_out_b, vort_out_w, vort_out_b,
                                            phi_weight, vort_weight, out);

    vel_kernel<<<(NB*D3 + 255)/256, 256>>>(out);

    const float* vel = out + OFF_VEL;
    advect_kernel<<<(NB*D3 + 255)/256, 256>>>(texture, texture, vel,  1.f, 0);
    advect_kernel<<<(NB*D3 + 255)/256, 256>>>(texture, texture, vel, -1.f, 1);
    advect_kernel<<<(NB*D3 + 255)/256, 256>>>(texture, texture, vel,  1.f, 2);

    f1_kernel<<<(D3 + 127)/128, 128>>>(ln_g, ln_b, ff_w1, ff_b1);
    f2_kernel<<<(D3 + 127)/128, 128>>>(ff_w2, ff_b2, out);
}

// round 4
// speedup vs baseline: 1.5192x; 1.5192x over previous
#include <cuda_runtime.h>
#include <math.h>

// ---------------- dimensions ----------------
#define NB 8          // batch*groups
#define S  66
#define S2 4356       // 66*66
#define S3 287496     // 66^3
#define HH 33
#define H2 1089       // 33*33
#define H3 35937      // 33^3
#define D3 262144     // 64^3

// output packing offsets (x, helmholtz, vel, vel_phi, vel_vort)
#define OFF_X     0
#define OFF_HELM  16777216
#define OFF_VEL   25977088
#define OFF_VPHI  32268544
#define OFF_VVORT 38560000

// ---------------- scratch (static device memory; no allocation APIs) ----------------
__device__ float g_f[3][NB*64*H3];     // encoder outputs: pm, pb, nm
__device__ float g_corr[NB*54*H3];     // correlation output
__device__ float g_c1[NB*16*H3];       // conv1 raw out (phi 0-7, vort 8-15)
__device__ float g_u1[NB*16*S3];       // upsampled (post BN1+relu)
__device__ float g_c2[NB*16*S3];       // conv2 raw out
__device__ float g_phi1[64*D3];        // advect pass 1
__device__ float g_comb[64*D3];        // 1.5*tex - 0.5*phi2
__device__ float g_pred[64*D3];        // final advect result
__device__ float g_gbuf[64*D3];        // FF hidden
__device__ float g_wp1[54*27*16];      // packed conv1 weights [(ic*27+tap)*16+oc]
__device__ float g_wp2[27*8*16];       // packed conv2 weights [(tap*8+icg)*16+oc]
__device__ float g_stat[64];           // mean1[16], istd1[16], mean2[16], istd2[16]
__device__ double g_part[16*32*2];     // partial reduction sums

// ---------------- weight packing ----------------
__global__ void pack_kernel(const float* __restrict__ pw1, const float* __restrict__ vw1,
                            const float* __restrict__ pw2, const float* __restrict__ vw2) {
    int i = blockIdx.x * blockDim.x + threadIdx.x;
    if (i < 54*27*16) {
        int oc = i & 15; int t = (i >> 4) % 27; int ic = (i >> 4) / 27;
        g_wp1[i] = (oc < 8) ? pw1[(oc*54 + ic)*27 + t] : vw1[((oc-8)*54 + ic)*27 + t];
    }
    if (i < 27*8*16) {
        int oc = i & 15; int icg = (i >> 4) % 8; int t = (i >> 4) / 8;
        g_wp2[i] = (oc < 8) ? pw2[(oc*8 + icg)*27 + t] : vw2[((oc-8)*8 + icg)*27 + t];
    }
}

// ---------------- encoder: conv3d stride 2, kernel 2, input = src*mul ----------------
// One thread per spatial position; computes ALL 64 output channels.
// 64 input taps loaded once into registers; weights (64x64) in smem read as float4.
__global__ void enc_kernel(const float* __restrict__ src, const float* __restrict__ mul,
                           const float* __restrict__ w, const float* __restrict__ b, int variant) {
    __shared__ float ws[4096];
    __shared__ float bs[64];
    for (int i = threadIdx.x; i < 4096; i += blockDim.x) ws[i] = w[i];
    if (threadIdx.x < 64) bs[threadIdx.x] = b[threadIdx.x];
    __syncthreads();

    int idx = blockIdx.x * blockDim.x + threadIdx.x;
    if (idx >= NB*H3) return;
    int p = idx % H3;
    int n = idx / H3;
    int z = p % HH, y = (p / HH) % HH, x = p / H2;
    int X = 2*x, Y = 2*y, Z = 2*z;

    float m[8];
#pragma unroll
    for (int t = 0; t < 8; t++) {
        int dx = t >> 2, dy = (t >> 1) & 1, dz = t & 1;
        m[t] = mul[((X+dx)*S + (Y+dy))*S + (Z+dz)];
    }

    float xin[64];
#pragma unroll
    for (int ic = 0; ic < 8; ic++) {
        int base = (n*8 + ic)*S3 + (X*S + Y)*S + Z;
#pragma unroll
        for (int t = 0; t < 8; t++) {
            int dx = t >> 2, dy = (t >> 1) & 1, dz = t & 1;
            xin[ic*8 + t] = src[base + (dx*S + dy)*S + dz] * m[t];
        }
    }

    float* outp = &g_f[variant][(n*64)*H3 + p];
    for (int oc = 0; oc < 64; oc++) {
        float acc = bs[oc];
        const float4* wv = reinterpret_cast<const float4*>(ws + (oc << 6));
#pragma unroll
        for (int q = 0; q < 16; q++) {
            float4 w4 = wv[q];
            acc += xin[q*4+0]*w4.x + xin[q*4+1]*w4.y + xin[q*4+2]*w4.z + xin[q*4+3]*w4.w;
        }
        outp[oc*H3] = acc;
    }
}

// ---------------- correlation: 2x27 channels ----------------
__global__ void corr_kernel() {
    int idx = blockIdx.x * blockDim.x + threadIdx.x;
    if (idx >= NB*H3) return;
    int p = idx % H3; int n = idx / H3;
    int z = p % HH, y = (p / HH) % HH, x = p / H2;

    const float* A0 = &g_f[0][n*64*H3 + p];
    const float* A1 = &g_f[1][n*64*H3 + p];
    const float* B  = &g_f[2][n*64*H3 + p];

    int off[9]; bool ok[9];
    {
        int s = 0;
        for (int di = -1; di <= 1; di++)
            for (int dj = -1; dj <= 1; dj++) {
                ok[s] = (x+di >= 0 && x+di < HH && y+dj >= 0 && y+dj < HH);
                off[s] = (di*HH + dj)*HH;
                s++;
            }
    }
    float acc[18];
#pragma unroll
    for (int s = 0; s < 18; s++) acc[s] = 0.f;

    for (int c = 0; c < 64; c++) {
        float a0 = A0[c*H3];
        float a1 = A1[c*H3];
        const float* Bc = B + c*H3;
#pragma unroll
        for (int s = 0; s < 9; s++) {
            float bv = ok[s] ? Bc[off[s]] : 0.f;
            acc[s]   += a0 * bv;
            acc[9+s] += a1 * bv;
        }
    }
    float zm0 = (z == HH-1) ? 0.f : 1.f;   // pm[0] zeroes last z slab
    float zm2 = (z == 0)    ? 0.f : 1.f;   // pm[2] zeroes first z slab
    for (int w = 0; w < 2; w++)
        for (int s = 0; s < 9; s++) {
            float d = acc[w*9 + s] * (1.f/64.f);
            g_corr[(n*54 + w*27 +      s)*H3 + p] = d * zm0;
            g_corr[(n*54 + w*27 +  9 + s)*H3 + p] = d;
            g_corr[(n*54 + w*27 + 18 + s)*H3 + p] = d * zm2;
        }
}

// ---------------- conv1: 54 -> 16, 3^3, pad 1, on 33^3 ----------------
__global__ void conv1_kernel() {
    extern __shared__ float ws[];
    for (int i = threadIdx.x; i < 54*27*16; i += blockDim.x) ws[i] = g_wp1[i];
    __syncthreads();

    int idx = blockIdx.x * blockDim.x + threadIdx.x;
    if (idx >= NB*H3) return;
    int p = idx % H3; int n = idx / H3;
    int z = p % HH, y = (p / HH) % HH, x = p / H2;

    float acc[16];
#pragma unroll
    for (int i = 0; i < 16; i++) acc[i] = 0.f;

    const float* cbase = g_corr + n*54*H3;
    for (int tap = 0; tap < 27; tap++) {
        int dx = tap/9 - 1, dy = (tap/3)%3 - 1, dz = tap%3 - 1;
        int xx = x+dx, yy = y+dy, zz = z+dz;
        if ((unsigned)xx >= (unsigned)HH || (unsigned)yy >= (unsigned)HH || (unsigned)zz >= (unsigned)HH) continue;
        int q = (xx*HH + yy)*HH + zz;
        for (int ic = 0; ic < 54; ic++) {
            float v = cbase[ic*H3 + q];
            const float4* wv = reinterpret_cast<const float4*>(ws + ((ic*27 + tap) << 4));
            float4 w0 = wv[0], w1 = wv[1], w2 = wv[2], w3 = wv[3];
            acc[0]  += v*w0.x; acc[1]  += v*w0.y; acc[2]  += v*w0.z; acc[3]  += v*w0.w;
            acc[4]  += v*w1.x; acc[5]  += v*w1.y; acc[6]  += v*w1.z; acc[7]  += v*w1.w;
            acc[8]  += v*w2.x; acc[9]  += v*w2.y; acc[10] += v*w2.z; acc[11] += v*w2.w;
            acc[12] += v*w3.x; acc[13] += v*w3.y; acc[14] += v*w3.z; acc[15] += v*w3.w;
        }
    }
#pragma unroll
    for (int oc = 0; oc < 16; oc++) g_c1[(n*16 + oc)*H3 + p] = acc[oc];
}

// ---------------- BN stats (two-stage deterministic) ----------------
__global__ void bn_stats_partial(int phase) {
    const float* src = phase ? g_c2 : g_c1;
    int spatial = phase ? S3 : H3;
    int total = NB * spatial;
    int ch = blockIdx.x, sl = blockIdx.y;
    double s = 0.0, s2 = 0.0;
    for (int i = sl*blockDim.x + threadIdx.x; i < total; i += 32*blockDim.x) {
        int n = i / spatial, p = i % spatial;
        float v = src[(n*16 + ch)*spatial + p];
        s += v; s2 += (double)v * v;
    }
    __shared__ double sh[512], sh2[512];
    sh[threadIdx.x] = s; sh2[threadIdx.x] = s2;
    __syncthreads();
    for (int st = 256; st > 0; st >>= 1) {
        if (threadIdx.x < st) { sh[threadIdx.x] += sh[threadIdx.x+st]; sh2[threadIdx.x] += sh2[threadIdx.x+st]; }
        __syncthreads();
    }
    if (threadIdx.x == 0) {
        g_part[(ch*32 + sl)*2 + 0] = sh[0];
        g_part[(ch*32 + sl)*2 + 1] = sh2[0];
    }
}

__global__ void bn_stats_final(int phase) {
    int ch = blockIdx.x;
    if (threadIdx.x != 0) return;
    int spatial = phase ? S3 : H3;
    double total = (double)NB * spatial;
    double s = 0.0, s2 = 0.0;
    for (int i = 0; i < 32; i++) { s += g_part[(ch*32+i)*2]; s2 += g_part[(ch*32+i)*2+1]; }
    double mean = s / total;
    double var = s2 / total - mean*mean;
    g_stat[phase*32 + ch]      = (float)mean;
    g_stat[phase*32 + 16 + ch] = (float)(1.0 / sqrt(var + 1e-5));
}

// ---------------- BN1 + relu + trilinear upsample x2 (align_corners) ----------------
__device__ __forceinline__ float bnrelu(float v, float sc, float sh) { return fmaxf(v*sc + sh, 0.f); }

__global__ void upsample_kernel(const float* __restrict__ g1p, const float* __restrict__ b1p,
                                const float* __restrict__ g1v, const float* __restrict__ b1v) {
    int idx = blockIdx.x * blockDim.x + threadIdx.x;
    if (idx >= NB*16*S3) return;
    int p = idx % S3; int ch = (idx / S3) % 16; int n = idx / (16*S3);
    int Z = p % S, Y = (p / S) % S, X = p / S2;

    float mean = g_stat[ch], istd = g_stat[16 + ch];
    float gg = (ch < 8) ? g1p[ch] : g1v[ch-8];
    float bb = (ch < 8) ? b1p[ch] : b1v[ch-8];
    float sc = istd * gg, sh = bb - mean * sc;

    const float SC = 32.f / 65.f;
    float sx = X * SC; int x0 = (int)sx; float fx = sx - x0; int x1 = min(x0+1, 32);
    float sy = Y * SC; int y0 = (int)sy; float fy = sy - y0; int y1 = min(y0+1, 32);
    float sz = Z * SC; int z0 = (int)sz; float fz = sz - z0; int z1 = min(z0+1, 32);

    const float* base = g_c1 + (n*16 + ch)*H3;
#define RD(xi,yi,zi) bnrelu(base[((xi)*HH+(yi))*HH+(zi)], sc, sh)
    float v =
      ((RD(x0,y0,z0)*(1-fx) + RD(x1,y0,z0)*fx)*(1-fy) + (RD(x0,y1,z0)*(1-fx) + RD(x1,y1,z0)*fx)*fy)*(1-fz)
    + ((RD(x0,y0,z1)*(1-fx) + RD(x1,y0,z1)*fx)*(1-fy) + (RD(x0,y1,z1)*(1-fx) + RD(x1,y1,z1)*fx)*fy)*fz;
#undef RD
    g_u1[idx] = v;
}

// ---------------- conv2: grouped 2x(8->8), 3^3, pad 1, on 66^3 ----------------
__global__ void conv2_kernel() {
    __shared__ float ws[27*8*16];
    for (int i = threadIdx.x; i < 27*8*16; i += blockDim.x) ws[i] = g_wp2[i];
    __syncthreads();

    int idx = blockIdx.x * blockDim.x + threadIdx.x;
    if (idx >= NB*S3) return;
    int p = idx % S3; int n = idx / S3;
    int z = p % S, y = (p / S) % S, x = p / S2;

    float acc[16];
#pragma unroll
    for (int i = 0; i < 16; i++) acc[i] = 0.f;

    const float* ubase = g_u1 + n*16*S3;
    for (int tap = 0; tap < 27; tap++) {
        int dx = tap/9 - 1, dy = (tap/3)%3 - 1, dz = tap%3 - 1;
        int xx = x+dx, yy = y+dy, zz = z+dz;
        if ((unsigned)xx >= (unsigned)S || (unsigned)yy >= (unsigned)S || (unsigned)zz >= (unsigned)S) continue;
        int q = (xx*S + yy)*S + zz;
#pragma unroll
        for (int icg = 0; icg < 8; icg++) {
            float vp = ubase[icg*S3 + q];
            float vv = ubase[(8+icg)*S3 + q];
            const float4* wv = reinterpret_cast<const float4*>(ws + ((tap*8 + icg) << 4));
            float4 w0 = wv[0], w1 = wv[1], w2 = wv[2], w3 = wv[3];
            acc[0]  += vp*w0.x; acc[1]  += vp*w0.y; acc[2]  += vp*w0.z; acc[3]  += vp*w0.w;
            acc[4]  += vp*w1.x; acc[5]  += vp*w1.y; acc[6]  += vp*w1.z; acc[7]  += vp*w1.w;
            acc[8]  += vv*w2.x; acc[9]  += vv*w2.y; acc[10] += vv*w2.z; acc[11] += vv*w2.w;
            acc[12] += vv*w3.x; acc[13] += vv*w3.y; acc[14] += vv*w3.z; acc[15] += vv*w3.w;
        }
    }
#pragma unroll
    for (int oc = 0; oc < 16; oc++) g_c2[(n*16 + oc)*S3 + p] = acc[oc];
}

// ---------------- BN2 + relu + 1x1 heads -> helmholtz (into d_out) ----------------
__global__ void helm_kernel(const float* __restrict__ g2p, const float* __restrict__ b2p,
                            const float* __restrict__ g2v, const float* __restrict__ b2v,
                            const float* __restrict__ pow_, const float* __restrict__ pob,
                            const float* __restrict__ vow,  const float* __restrict__ vob,
                            const float* __restrict__ phiw, const float* __restrict__ vortw,
                            float* __restrict__ out) {
    int idx = blockIdx.x * blockDim.x + threadIdx.x;
    if (idx >= NB*S3) return;
    int p = idx % S3; int n = idx / S3;

    float y[16];
#pragma unroll
    for (int c = 0; c < 16; c++) {
        float mean = g_stat[32 + c], istd = g_stat[48 + c];
        float gg = (c < 8) ? g2p[c] : g2v[c-8];
        float bb = (c < 8) ? b2p[c] : b2v[c-8];
        float v = (g_c2[(n*16 + c)*S3 + p] - mean) * istd * gg + bb;
        y[c] = fmaxf(v, 0.f);
    }
    float ph = pob[0];
#pragma unroll
    for (int c = 0; c < 8; c++) ph += y[c] * pow_[c];
    ph *= phiw[0];
    out[OFF_HELM + (n*4)*S3 + p] = ph;
    float vscale = vortw[0] * 66.f;
#pragma unroll
    for (int r = 0; r < 3; r++) {
        float v = vob[r];
#pragma unroll
        for (int c = 0; c < 8; c++) v += y[8+c] * vow[r*8 + c];
        out[OFF_HELM + (n*4 + 1 + r)*S3 + p] = v * vscale;
    }
}

// ---------------- velocity stencils (into d_out) ----------------
__device__ __forceinline__ float HV(const float* hm, int ch, int x, int y, int z) {
    return hm[ch*S3 + (x*S + y)*S + z];
}

__global__ void vel_kernel(float* __restrict__ out) {
    int idx = blockIdx.x * blockDim.x + threadIdx.x;
    if (idx >= NB*D3) return;
    int p = idx % D3; int n = idx / D3;
    int k = p & 63, j = (p >> 6) & 63, i = p >> 12;
    const float* hm = out + OFF_HELM + n*4*S3;

    // vel_phi
    float vp0 = 0.5f * (HV(hm,0, 1+i, 1+j, k+2) - HV(hm,0, 1+i, 1+j, k));
    float vp1 = 0.5f * (HV(hm,0, 1+i, j+2, 1+k) - HV(hm,0, 1+i, j,   1+k));
    float vp2 = 0.5f * (HV(hm,0, i+2, 1+j, 1+k) - HV(hm,0, i,   1+j, 1+k));

    // vel_vort (s0=ch1, s1=ch2, s2=ch3)
    float ua = (HV(hm,2, 2+i,1+j,k+1) - HV(hm,2, 1+i,1+j,k+1)) - (HV(hm,1, 1+i,2+j,k+1) - HV(hm,1, 1+i,1+j,k+1));
    float ub = (HV(hm,2, 2+i,1+j,k  ) - HV(hm,2, 1+i,1+j,k  )) - (HV(hm,1, 1+i,2+j,k  ) - HV(hm,1, 1+i,1+j,k  ));
    float vv0 = 0.5f * (ua + ub);
    float va = (HV(hm,1, 1+i,j+1,k+2) - HV(hm,1, 1+i,j+1,k+1)) - (HV(hm,3, i+2,j+1,k+1) - HV(hm,3, i+1,j+1,k+1));
    float vb = (HV(hm,1, 1+i,j,  k+2) - HV(hm,1, 1+i,j,  k+1)) - (HV(hm,3, i+2,j,  k+1) - HV(hm,3, i+1,j,  k+1));
    float vv1 = 0.5f * (va + vb);
    float wa = (HV(hm,3, i+1,j+2,k+1) - HV(hm,3, i+1,j+1,k+1)) - (HV(hm,2, i+1,j+1,k+2) - HV(hm,2, i+1,j+1,k+1));
    float wb = (HV(hm,3, i,  j+2,k+1) - HV(hm,3, i,  j+1,k+1)) - (HV(hm,2, i,  j+1,k+2) - HV(hm,2, i,  j+1,k+1));
    float vv2 = 0.5f * (wa + wb);

    int b = n*3*D3 + p;
    out[OFF_VPHI  + b        ] = vp0;
    out[OFF_VPHI  + b + D3   ] = vp1;
    out[OFF_VPHI  + b + 2*D3 ] = vp2;
    out[OFF_VVORT + b        ] = vv0;
    out[OFF_VVORT + b + D3   ] = vv1;
    out[OFF_VVORT + b + 2*D3 ] = vv2;
    out[OFF_VEL   + b        ] = vp0 + vv0;
    out[OFF_VEL   + b + D3   ] = vp1 + vv1;
    out[OFF_VEL   + b + 2*D3 ] = vp2 + vv2;
}

// ---------------- BFECC advect passes ----------------
// mode 0: dst=g_phi1,  src=texture,  sgn=+1
// mode 1: dst=g_comb,  src=g_phi1,   sgn=-1, combine: 1.5*tex - 0.5*sample
// mode 2: dst=g_pred,  src=g_comb,   sgn=+1
__global__ void advect_kernel(const float* __restrict__ ext_src, const float* __restrict__ tex,
                              const float* __restrict__ vel, float sgn, int mode) {
    int idx = blockIdx.x * blockDim.x + threadIdx.x;
    if (idx >= NB*D3) return;
    int p = idx % D3; int n = idx / D3;
    int k = p & 63, j = (p >> 6) & 63, i = p >> 12;

    float v0 = vel[(n*3    )*D3 + p];
    float v1 = vel[(n*3 + 1)*D3 + p];
    float v2 = vel[(n*3 + 2)*D3 + p];
    float px = (float)i - sgn*v2;
    float py = (float)j - sgn*v1;
    float pz = (float)k - sgn*v0;
    px = fminf(fmaxf(px, 0.f), 63.f);
    py = fminf(fmaxf(py, 0.f), 63.f);
    pz = fminf(fmaxf(pz, 0.f), 63.f);
    int x0 = (int)px; float fx = px - x0; int x1 = min(x0+1, 63);
    int y0 = (int)py; float fy = py - y0; int y1 = min(y0+1, 63);
    int z0 = (int)pz; float fz = pz - z0; int z1 = min(z0+1, 63);

    float w000 = (1-fx)*(1-fy)*(1-fz), w001 = (1-fx)*(1-fy)*fz;
    float w010 = (1-fx)*fy*(1-fz),     w011 = (1-fx)*fy*fz;
    float w100 = fx*(1-fy)*(1-fz),     w101 = fx*(1-fy)*fz;
    float w110 = fx*fy*(1-fz),         w111 = fx*fy*fz;

    int b00 = (x0*64 + y0)*64, b01 = (x0*64 + y1)*64;
    int b10 = (x1*64 + y0)*64, b11 = (x1*64 + y1)*64;

    const float* src = (mode == 0) ? ext_src : ((mode == 1) ? g_phi1 : g_comb);
    float* dst = (mode == 0) ? g_phi1 : ((mode == 1) ? g_comb : g_pred);

#pragma unroll
    for (int c = 0; c < 8; c++) {
        const float* s = src + (n*8 + c)*D3;
        float v = w000*s[b00+z0] + w001*s[b00+z1] + w010*s[b01+z0] + w011*s[b01+z1]
                + w100*s[b10+z0] + w101*s[b10+z1] + w110*s[b11+z0] + w111*s[b11+z1];
        if (mode == 1) v = 1.5f * tex[(n*8 + c)*D3 + p] - 0.5f * v;
        dst[(n*8 + c)*D3 + p] = v;
    }
}

// ---------------- LN + FF stage 1 (LN, @W1+b1, exact GELU) ----------------
__global__ void f1_kernel(const float* __restrict__ lng, const float* __restrict__ lnb,
                          const float* __restrict__ w1, const float* __restrict__ b1) {
    __shared__ float W[4096], Bv[64], G[64], Bt[64];
    for (int i = threadIdx.x; i < 4096; i += blockDim.x) W[i] = w1[i];
    if (threadIdx.x < 64) { Bv[threadIdx.x] = b1[threadIdx.x]; G[threadIdx.x] = lng[threadIdx.x]; Bt[threadIdx.x] = lnb[threadIdx.x]; }
    __syncthreads();

    int p = blockIdx.x * blockDim.x + threadIdx.x;
    if (p >= D3) return;
    float h[64]; float s = 0.f, s2 = 0.f;
#pragma unroll
    for (int c = 0; c < 64; c++) { float v = g_pred[c*D3 + p]; h[c] = v; s += v; s2 += v*v; }
    float mean = s * (1.f/64.f);
    float var  = s2 * (1.f/64.f) - mean*mean;
    float is = rsqrtf(var + 1e-5f);
#pragma unroll
    for (int c = 0; c < 64; c++) h[c] = (h[c] - mean) * is * G[c] + Bt[c];

    for (int jj = 0; jj < 64; jj++) {
        float a = Bv[jj];
#pragma unroll
        for (int ii = 0; ii < 64; ii++) a += h[ii] * W[ii*64 + jj];
        float g = 0.5f * a * (1.f + erff(a * 0.70710678118f));
        g_gbuf[jj*D3 + p] = g;
    }
}

// ---------------- FF stage 2 (@W2+b2, residual -> d_out x) ----------------
__global__ void f2_kernel(const float* __restrict__ w2, const float* __restrict__ b2,
                          float* __restrict__ out) {
    __shared__ float W[4096], Bv[64];
    for (int i = threadIdx.x; i < 4096; i += blockDim.x) W[i] = w2[i];
    if (threadIdx.x < 64) Bv[threadIdx.x] = b2[threadIdx.x];
    __syncthreads();

    int p = blockIdx.x * blockDim.x + threadIdx.x;
    if (p >= D3) return;
    float g[64];
#pragma unroll
    for (int c = 0; c < 64; c++) g[c] = g_gbuf[c*D3 + p];
    for (int jj = 0; jj < 64; jj++) {
        float a = Bv[jj];
#pragma unroll
        for (int ii = 0; ii < 64; ii++) a += g[ii] * W[ii*64 + jj];
        out[OFF_X + jj*D3 + p] = g_pred[jj*D3 + p] + a;
    }
}

// ---------------- host launch ----------------
extern "C" void kernel_launch(void* const* d_in, const int* in_sizes, int n_in,
                              void* d_out, int out_size) {
    const float* prev      = (const float*)d_in[0];
    const float* nxt       = (const float*)d_in[1];
    const float* texture   = (const float*)d_in[2];
    const float* mask      = (const float*)d_in[3];
    const float* boundary  = (const float*)d_in[4];
    const float* enc_w     = (const float*)d_in[5];
    const float* enc_b     = (const float*)d_in[6];
    const float* phi_c1_w  = (const float*)d_in[7];
    const float* phi_bn1_g = (const float*)d_in[8];
    const float* phi_bn1_b = (const float*)d_in[9];
    const float* phi_c2_w  = (const float*)d_in[10];
    const float* phi_bn2_g = (const float*)d_in[11];
    const float* phi_bn2_b = (const float*)d_in[12];
    const float* phi_out_w = (const float*)d_in[13];
    const float* phi_out_b = (const float*)d_in[14];
    const float* vort_c1_w = (const float*)d_in[15];
    const float* vort_bn1_g= (const float*)d_in[16];
    const float* vort_bn1_b= (const float*)d_in[17];
    const float* vort_c2_w = (const float*)d_in[18];
    const float* vort_bn2_g= (const float*)d_in[19];
    const float* vort_bn2_b= (const float*)d_in[20];
    const float* vort_out_w= (const float*)d_in[21];
    const float* vort_out_b= (const float*)d_in[22];
    const float* phi_weight= (const float*)d_in[23];
    const float* vort_weight=(const float*)d_in[24];
    const float* ln_g      = (const float*)d_in[25];
    const float* ln_b      = (const float*)d_in[26];
    const float* ff_w1     = (const float*)d_in[27];
    const float* ff_b1     = (const float*)d_in[28];
    const float* ff_w2     = (const float*)d_in[29];
    const float* ff_b2     = (const float*)d_in[30];
    float* out = (float*)d_out;

    pack_kernel<<<(54*27*16 + 255)/256, 256>>>(phi_c1_w, vort_c1_w, phi_c2_w, vort_c2_w);

    int encBlocks = (NB*H3 + 255)/256;
    enc_kernel<<<encBlocks, 256>>>(prev, mask,     enc_w, enc_b, 0);
    enc_kernel<<<encBlocks, 256>>>(prev, boundary, enc_w, enc_b, 1);
    enc_kernel<<<encBlocks, 256>>>(nxt,  mask,     enc_w, enc_b, 2);

    corr_kernel<<<(NB*H3 + 255)/256, 256>>>();

    cudaFuncSetAttribute(conv1_kernel, cudaFuncAttributeMaxDynamicSharedMemorySize, 54*27*16*4);
    conv1_kernel<<<(NB*H3 + 255)/256, 256, 54*27*16*4>>>();

    bn_stats_partial<<<dim3(16, 32), 512>>>(0);
    bn_stats_final<<<16, 32>>>(0);

    int upN = NB*16*S3;
    upsample_kernel<<<(upN + 255)/256, 256>>>(phi_bn1_g, phi_bn1_b, vort_bn1_g, vort_bn1_b);

    conv2_kernel<<<(NB*S3 + 255)/256, 256>>>();

    bn_stats_partial<<<dim3(16, 32), 512>>>(1);
    bn_stats_final<<<16, 32>>>(1);

    helm_kernel<<<(NB*S3 + 255)/256, 256>>>(phi_bn2_g, phi_bn2_b, vort_bn2_g, vort_bn2_b,
                                            phi_out_w, phi_out_b, vort_out_w, vort_out_b,
                                            phi_weight, vort_weight, out);

    vel_kernel<<<(NB*D3 + 255)/256, 256>>>(out);

    const float* vel = out + OFF_VEL;
    advect_kernel<<<(NB*D3 + 255)/256, 256>>>(texture, texture, vel,  1.f, 0);
    advect_kernel<<<(NB*D3 + 255)/256, 256>>>(texture, texture, vel, -1.f, 1);
    advect_kernel<<<(NB*D3 + 255)/256, 256>>>(texture, texture, vel,  1.f, 2);

    f1_kernel<<<(D3 + 127)/128, 128>>>(ln_g, ln_b, ff_w1, ff_b1);
    f2_kernel<<<(D3 + 127)/128, 128>>>(ff_w2, ff_b2, out);
}

// round 6
// speedup vs baseline: 1.8613x; 1.2252x over previous
#include <cuda_runtime.h>
#include <math.h>

// ---------------- dimensions ----------------
#define NB 8          // batch*groups
#define S  66
#define S2 4356       // 66*66
#define S3 287496     // 66^3
#define HH 33
#define H2 1089       // 33*33
#define H3 35937      // 33^3
#define D3 262144     // 64^3

// output packing offsets (x, helmholtz, vel, vel_phi, vel_vort)
#define OFF_X     0
#define OFF_HELM  16777216
#define OFF_VEL   25977088
#define OFF_VPHI  32268544
#define OFF_VVORT 38560000

#define WC1_PACK 7776          // 18*27*16
// ---------------- scratch (static device memory; no allocation APIs) ----------------
__device__ float g_f[3][NB*64*H3];     // encoder outputs: pm, pb, nm
__device__ float g_corr[NB*18*H3];     // correlation output (18 distinct channels)
__device__ float g_c1[NB*16*H3];       // conv1 raw out (phi 0-7, vort 8-15)
__device__ float g_u1[NB*16*S3];       // upsampled (post BN1+relu)
__device__ float g_c2[NB*16*S3];       // conv2 raw out
__device__ float g_phi1[64*D3];        // advect pass 1
__device__ float g_comb[64*D3];        // 1.5*tex - 0.5*phi2
__device__ float g_pred[64*D3];        // final advect result
__device__ float g_gbuf[64*D3];        // FF hidden
__device__ float g_wc1[3*WC1_PACK];    // conv1 summed packs: [pack][(tap*18+ic)*16+oc]
__device__ float g_wp2[27*8*16];       // packed conv2 weights [(tap*8+icg)*16+oc]
__device__ float g_stat[64];           // mean1[16], istd1[16], mean2[16], istd2[16]
__device__ double g_part[16*32*2];     // partial reduction sums

// ---------------- weight packing ----------------
// conv1: channels c, c+9, c+18 of the 54-ch corr input carry the SAME value d,
// masked by (zz!=32), 1, (zz!=0). Precompute summed packs:
//   pack0 (interior): W[c0]+W[c1]+W[c2]
//   pack1 (zz==0):    W[c0]+W[c1]
//   pack2 (zz==32):   W[c1]+W[c2]
__global__ void pack_kernel(const float* __restrict__ pw1, const float* __restrict__ vw1,
                            const float* __restrict__ pw2, const float* __restrict__ vw2) {
    int i = blockIdx.x * blockDim.x + threadIdx.x;
    if (i < 3*WC1_PACK) {
        int pack = i / WC1_PACK; int r = i % WC1_PACK;
        int oc = r & 15; int t18 = r >> 4; int ic = t18 % 18; int tap = t18 / 18;
        int w = ic / 9, s = ic % 9;
        int c0 = w*27 + s, c1 = c0 + 9, c2 = c0 + 18;
        const float* src = (oc < 8) ? pw1 : vw1;
        int o = (oc < 8) ? oc : oc - 8;
        float W0 = src[(o*54 + c0)*27 + tap];
        float W1 = src[(o*54 + c1)*27 + tap];
        float W2 = src[(o*54 + c2)*27 + tap];
        float v = (pack == 0) ? (W0 + W1 + W2) : ((pack == 1) ? (W0 + W1) : (W1 + W2));
        g_wc1[i] = v;
    }
    if (i < 27*8*16) {
        int oc = i & 15; int icg = (i >> 4) % 8; int t = (i >> 4) / 8;
        g_wp2[i] = (oc < 8) ? pw2[(oc*8 + icg)*27 + t] : vw2[((oc-8)*8 + icg)*27 + t];
    }
}

// ---------------- encoder: conv3d stride 2, kernel 2, input = src*mul ----------------
__global__ void enc_kernel(const float* __restrict__ src, const float* __restrict__ mul,
                           const float* __restrict__ w, const float* __restrict__ b, int variant) {
    __shared__ float ws[4096];
    __shared__ float bs[64];
    for (int i = threadIdx.x; i < 4096; i += blockDim.x) ws[i] = w[i];
    if (threadIdx.x < 64) bs[threadIdx.x] = b[threadIdx.x];
    __syncthreads();

    int idx = blockIdx.x * blockDim.x + threadIdx.x;
    if (idx >= NB*H3) return;
    int p = idx % H3;
    int n = idx / H3;
    int z = p % HH, y = (p / HH) % HH, x = p / H2;
    int X = 2*x, Y = 2*y, Z = 2*z;

    float m[8];
#pragma unroll
    for (int t = 0; t < 8; t++) {
        int dx = t >> 2, dy = (t >> 1) & 1, dz = t & 1;
        m[t] = mul[((X+dx)*S + (Y+dy))*S + (Z+dz)];
    }

    float xin[64];
#pragma unroll
    for (int ic = 0; ic < 8; ic++) {
        int base = (n*8 + ic)*S3 + (X*S + Y)*S + Z;
#pragma unroll
        for (int t = 0; t < 8; t++) {
            int dx = t >> 2, dy = (t >> 1) & 1, dz = t & 1;
            xin[ic*8 + t] = src[base + (dx*S + dy)*S + dz] * m[t];
        }
    }

    float* outp = &g_f[variant][(n*64)*H3 + p];
    for (int oc = 0; oc < 64; oc++) {
        float acc = bs[oc];
        const float4* wv = reinterpret_cast<const float4*>(ws + (oc << 6));
#pragma unroll
        for (int q = 0; q < 16; q++) {
            float4 w4 = wv[q];
            acc += xin[q*4+0]*w4.x + xin[q*4+1]*w4.y + xin[q*4+2]*w4.z + xin[q*4+3]*w4.w;
        }
        outp[oc*H3] = acc;
    }
}

// ---------------- correlation: 18 distinct channels (masks folded into conv1 weights) ----------------
__global__ void corr_kernel() {
    int idx = blockIdx.x * blockDim.x + threadIdx.x;
    if (idx >= NB*H3) return;
    int p = idx % H3; int n = idx / H3;
    int y = (p / HH) % HH, x = p / H2;

    const float* A0 = &g_f[0][n*64*H3 + p];
    const float* A1 = &g_f[1][n*64*H3 + p];
    const float* B  = &g_f[2][n*64*H3 + p];

    int off[9]; bool ok[9];
    {
        int s = 0;
        for (int di = -1; di <= 1; di++)
            for (int dj = -1; dj <= 1; dj++) {
                ok[s] = (x+di >= 0 && x+di < HH && y+dj >= 0 && y+dj < HH);
                off[s] = (di*HH + dj)*HH;
                s++;
            }
    }
    float acc[18];
#pragma unroll
    for (int s = 0; s < 18; s++) acc[s] = 0.f;

    for (int c = 0; c < 64; c++) {
        float a0 = A0[c*H3];
        float a1 = A1[c*H3];
        const float* Bc = B + c*H3;
#pragma unroll
        for (int s = 0; s < 9; s++) {
            float bv = ok[s] ? Bc[off[s]] : 0.f;
            acc[s]   += a0 * bv;
            acc[9+s] += a1 * bv;
        }
    }
#pragma unroll
    for (int s = 0; s < 18; s++)
        g_corr[(n*18 + s)*H3 + p] = acc[s] * (1.f/64.f);
}

// ---------------- conv1: effective 18 -> 16, 3^3, pad 1, on 33^3, z-masked weight packs ----------------
__global__ void conv1_kernel() {
    extern __shared__ float ws[];
    for (int i = threadIdx.x; i < 3*WC1_PACK; i += blockDim.x) ws[i] = g_wc1[i];
    __syncthreads();

    int idx = blockIdx.x * blockDim.x + threadIdx.x;
    if (idx >= NB*H3) return;
    int p = idx % H3; int n = idx / H3;
    int z = p % HH, y = (p / HH) % HH, x = p / H2;

    float acc[16];
#pragma unroll
    for (int i = 0; i < 16; i++) acc[i] = 0.f;

    const float* cbase = g_corr + n*18*H3;
    for (int tap = 0; tap < 27; tap++) {
        int dx = tap/9 - 1, dy = (tap/3)%3 - 1, dz = tap%3 - 1;
        int xx = x+dx, yy = y+dy, zz = z+dz;
        if ((unsigned)xx >= (unsigned)HH || (unsigned)yy >= (unsigned)HH || (unsigned)zz >= (unsigned)HH) continue;
        int q = (xx*HH + yy)*HH + zz;
        int sel = (zz == 0) ? 1 : ((zz == HH-1) ? 2 : 0);
        const float* wt = ws + sel*WC1_PACK + tap*288;
#pragma unroll
        for (int ic = 0; ic < 18; ic++) {
            float v = cbase[ic*H3 + q];
            const float4* wv = reinterpret_cast<const float4*>(wt + (ic << 4));
            float4 w0 = wv[0], w1 = wv[1], w2 = wv[2], w3 = wv[3];
            acc[0]  += v*w0.x; acc[1]  += v*w0.y; acc[2]  += v*w0.z; acc[3]  += v*w0.w;
            acc[4]  += v*w1.x; acc[5]  += v*w1.y; acc[6]  += v*w1.z; acc[7]  += v*w1.w;
            acc[8]  += v*w2.x; acc[9]  += v*w2.y; acc[10] += v*w2.z; acc[11] += v*w2.w;
            acc[12] += v*w3.x; acc[13] += v*w3.y; acc[14] += v*w3.z; acc[15] += v*w3.w;
        }
    }
#pragma unroll
    for (int oc = 0; oc < 16; oc++) g_c1[(n*16 + oc)*H3 + p] = acc[oc];
}

// ---------------- BN stats (two-stage deterministic) ----------------
__global__ void bn_stats_partial(int phase) {
    const float* src = phase ? g_c2 : g_c1;
    int spatial = phase ? S3 : H3;
    int total = NB * spatial;
    int ch = blockIdx.x, sl = blockIdx.y;
    double s = 0.0, s2 = 0.0;
    for (int i = sl*blockDim.x + threadIdx.x; i < total; i += 32*blockDim.x) {
        int n = i / spatial, p = i % spatial;
        float v = src[(n*16 + ch)*spatial + p];
        s += v; s2 += (double)v * v;
    }
    __shared__ double sh[512], sh2[512];
    sh[threadIdx.x] = s; sh2[threadIdx.x] = s2;
    __syncthreads();
    for (int st = 256; st > 0; st >>= 1) {
        if (threadIdx.x < st) { sh[threadIdx.x] += sh[threadIdx.x+st]; sh2[threadIdx.x] += sh2[threadIdx.x+st]; }
        __syncthreads();
    }
    if (threadIdx.x == 0) {
        g_part[(ch*32 + sl)*2 + 0] = sh[0];
        g_part[(ch*32 + sl)*2 + 1] = sh2[0];
    }
}

__global__ void bn_stats_final(int phase) {
    int ch = blockIdx.x;
    if (threadIdx.x != 0) return;
    int spatial = phase ? S3 : H3;
    double total = (double)NB * spatial;
    double s = 0.0, s2 = 0.0;
    for (int i = 0; i < 32; i++) { s += g_part[(ch*32+i)*2]; s2 += g_part[(ch*32+i)*2+1]; }
    double mean = s / total;
    double var = s2 / total - mean*mean;
    g_stat[phase*32 + ch]      = (float)mean;
    g_stat[phase*32 + 16 + ch] = (float)(1.0 / sqrt(var + 1e-5));
}

// ---------------- BN1 + relu + trilinear upsample x2 (align_corners) ----------------
__device__ __forceinline__ float bnrelu(float v, float sc, float sh) { return fmaxf(v*sc + sh, 0.f); }

__global__ void upsample_kernel(const float* __restrict__ g1p, const float* __restrict__ b1p,
                                const float* __restrict__ g1v, const float* __restrict__ b1v) {
    int idx = blockIdx.x * blockDim.x + threadIdx.x;
    if (idx >= NB*16*S3) return;
    int p = idx % S3; int ch = (idx / S3) % 16; int n = idx / (16*S3);
    int Z = p % S, Y = (p / S) % S, X = p / S2;

    float mean = g_stat[ch], istd = g_stat[16 + ch];
    float gg = (ch < 8) ? g1p[ch] : g1v[ch-8];
    float bb = (ch < 8) ? b1p[ch] : b1v[ch-8];
    float sc = istd * gg, sh = bb - mean * sc;

    const float SC = 32.f / 65.f;
    float sx = X * SC; int x0 = (int)sx; float fx = sx - x0; int x1 = min(x0+1, 32);
    float sy = Y * SC; int y0 = (int)sy; float fy = sy - y0; int y1 = min(y0+1, 32);
    float sz = Z * SC; int z0 = (int)sz; float fz = sz - z0; int z1 = min(z0+1, 32);

    const float* base = g_c1 + (n*16 + ch)*H3;
#define RD(xi,yi,zi) bnrelu(base[((xi)*HH+(yi))*HH+(zi)], sc, sh)
    float v =
      ((RD(x0,y0,z0)*(1-fx) + RD(x1,y0,z0)*fx)*(1-fy) + (RD(x0,y1,z0)*(1-fx) + RD(x1,y1,z0)*fx)*fy)*(1-fz)
    + ((RD(x0,y0,z1)*(1-fx) + RD(x1,y0,z1)*fx)*(1-fy) + (RD(x0,y1,z1)*(1-fx) + RD(x1,y1,z1)*fx)*fy)*fz;
#undef RD
    g_u1[idx] = v;
}

// ---------------- conv2: grouped 2x(8->8), 3^3, pad 1, on 66^3, z-vectorized x2 ----------------
__global__ void conv2_kernel() {
    __shared__ float ws[27*8*16];
    for (int i = threadIdx.x; i < 27*8*16; i += blockDim.x) ws[i] = g_wp2[i];
    __syncthreads();

    int idx = blockIdx.x * blockDim.x + threadIdx.x;
    if (idx >= NB*S*S*33) return;
    int zt = idx % 33;
    int y  = (idx / 33) % S;
    int x  = (idx / (33*S)) % S;
    int n  = idx / (33*S*S);
    int z0 = 2*zt;

    float acc[2][16];
#pragma unroll
    for (int pp = 0; pp < 2; pp++)
#pragma unroll
        for (int i = 0; i < 16; i++) acc[pp][i] = 0.f;

    const float* ubase = g_u1 + n*16*S3;
    bool zlo = (zt == 0);          // z0-1 invalid
    bool zhi = (zt == 32);         // z0+2 == 66 invalid

#pragma unroll
    for (int dx = -1; dx <= 1; dx++) {
        int xx = x + dx;
        if ((unsigned)xx >= (unsigned)S) continue;
#pragma unroll
        for (int dy = -1; dy <= 1; dy++) {
            int yy = y + dy;
            if ((unsigned)yy >= (unsigned)S) continue;
            int tap0 = ((dx+1)*3 + (dy+1))*3;
            const float* col = ubase + (xx*S + yy)*S + z0;
#pragma unroll
            for (int icg = 0; icg < 8; icg++) {
                const float* cp = col + icg*S3;
                const float* cv = col + (8+icg)*S3;
                float inp[4], inv[4];
                inp[0] = zlo ? 0.f : cp[-1];  inv[0] = zlo ? 0.f : cv[-1];
                inp[1] = cp[0];               inv[1] = cv[0];
                inp[2] = cp[1];               inv[2] = cv[1];
                inp[3] = zhi ? 0.f : cp[2];   inv[3] = zhi ? 0.f : cv[2];
#pragma unroll
                for (int dz = 0; dz < 3; dz++) {
                    const float4* wv = reinterpret_cast<const float4*>(ws + (((tap0+dz)*8 + icg) << 4));
                    float4 w0 = wv[0], w1 = wv[1], w2 = wv[2], w3 = wv[3];
#pragma unroll
                    for (int pp = 0; pp < 2; pp++) {
                        float vp = inp[pp+dz];
                        float vv = inv[pp+dz];
                        acc[pp][0]  += vp*w0.x; acc[pp][1]  += vp*w0.y; acc[pp][2]  += vp*w0.z; acc[pp][3]  += vp*w0.w;
                        acc[pp][4]  += vp*w1.x; acc[pp][5]  += vp*w1.y; acc[pp][6]  += vp*w1.z; acc[pp][7]  += vp*w1.w;
                        acc[pp][8]  += vv*w2.x; acc[pp][9]  += vv*w2.y; acc[pp][10] += vv*w2.z; acc[pp][11] += vv*w2.w;
                        acc[pp][12] += vv*w3.x; acc[pp][13] += vv*w3.y; acc[pp][14] += vv*w3.z; acc[pp][15] += vv*w3.w;
                    }
                }
            }
        }
    }
    int ob = (x*S + y)*S + z0;
#pragma unroll
    for (int oc = 0; oc < 16; oc++) {
        float2 v; v.x = acc[0][oc]; v.y = acc[1][oc];
        *reinterpret_cast<float2*>(&g_c2[(n*16 + oc)*S3 + ob]) = v;
    }
}

// ---------------- BN2 + relu + 1x1 heads -> helmholtz (into d_out) ----------------
__global__ void helm_kernel(const float* __restrict__ g2p, const float* __restrict__ b2p,
                            const float* __restrict__ g2v, const float* __restrict__ b2v,
                            const float* __restrict__ pow_, const float* __restrict__ pob,
                            const float* __restrict__ vow,  const float* __restrict__ vob,
                            const float* __restrict__ phiw, const float* __restrict__ vortw,
                            float* __restrict__ out) {
    int idx = blockIdx.x * blockDim.x + threadIdx.x;
    if (idx >= NB*S3) return;
    int p = idx % S3; int n = idx / S3;

    float y[16];
#pragma unroll
    for (int c = 0; c < 16; c++) {
        float mean = g_stat[32 + c], istd = g_stat[48 + c];
        float gg = (c < 8) ? g2p[c] : g2v[c-8];
        float bb = (c < 8) ? b2p[c] : b2v[c-8];
        float v = (g_c2[(n*16 + c)*S3 + p] - mean) * istd * gg + bb;
        y[c] = fmaxf(v, 0.f);
    }
    float ph = pob[0];
#pragma unroll
    for (int c = 0; c < 8; c++) ph += y[c] * pow_[c];
    ph *= phiw[0];
    out[OFF_HELM + (n*4)*S3 + p] = ph;
    float vscale = vortw[0] * 66.f;
#pragma unroll
    for (int r = 0; r < 3; r++) {
        float v = vob[r];
#pragma unroll
        for (int c = 0; c < 8; c++) v += y[8+c] * vow[r*8 + c];
        out[OFF_HELM + (n*4 + 1 + r)*S3 + p] = v * vscale;
    }
}

// ---------------- velocity stencils (into d_out) ----------------
__device__ __forceinline__ float HV(const float* hm, int ch, int x, int y, int z) {
    return hm[ch*S3 + (x*S + y)*S + z];
}

__global__ void vel_kernel(float* __restrict__ out) {
    int idx = blockIdx.x * blockDim.x + threadIdx.x;
    if (idx >= NB*D3) return;
    int p = idx % D3; int n = idx / D3;
    int k = p & 63, j = (p >> 6) & 63, i = p >> 12;
    const float* hm = out + OFF_HELM + n*4*S3;

    // vel_phi
    float vp0 = 0.5f * (HV(hm,0, 1+i, 1+j, k+2) - HV(hm,0, 1+i, 1+j, k));
    float vp1 = 0.5f * (HV(hm,0, 1+i, j+2, 1+k) - HV(hm,0, 1+i, j,   1+k));
    float vp2 = 0.5f * (HV(hm,0, i+2, 1+j, 1+k) - HV(hm,0, i,   1+j, 1+k));

    // vel_vort (s0=ch1, s1=ch2, s2=ch3)
    float ua = (HV(hm,2, 2+i,1+j,k+1) - HV(hm,2, 1+i,1+j,k+1)) - (HV(hm,1, 1+i,2+j,k+1) - HV(hm,1, 1+i,1+j,k+1));
    float ub = (HV(hm,2, 2+i,1+j,k  ) - HV(hm,2, 1+i,1+j,k  )) - (HV(hm,1, 1+i,2+j,k  ) - HV(hm,1, 1+i,1+j,k  ));
    float vv0 = 0.5f * (ua + ub);
    float va = (HV(hm,1, 1+i,j+1,k+2) - HV(hm,1, 1+i,j+1,k+1)) - (HV(hm,3, i+2,j+1,k+1) - HV(hm,3, i+1,j+1,k+1));
    float vb = (HV(hm,1, 1+i,j,  k+2) - HV(hm,1, 1+i,j,  k+1)) - (HV(hm,3, i+2,j,  k+1) - HV(hm,3, i+1,j,  k+1));
    float vv1 = 0.5f * (va + vb);
    float wa = (HV(hm,3, i+1,j+2,k+1) - HV(hm,3, i+1,j+1,k+1)) - (HV(hm,2, i+1,j+1,k+2) - HV(hm,2, i+1,j+1,k+1));
    float wb = (HV(hm,3, i,  j+2,k+1) - HV(hm,3, i,  j+1,k+1)) - (HV(hm,2, i,  j+1,k+2) - HV(hm,2, i,  j+1,k+1));
    float vv2 = 0.5f * (wa + wb);

    int b = n*3*D3 + p;
    out[OFF_VPHI  + b        ] = vp0;
    out[OFF_VPHI  + b + D3   ] = vp1;
    out[OFF_VPHI  + b + 2*D3 ] = vp2;
    out[OFF_VVORT + b        ] = vv0;
    out[OFF_VVORT + b + D3   ] = vv1;
    out[OFF_VVORT + b + 2*D3 ] = vv2;
    out[OFF_VEL   + b        ] = vp0 + vv0;
    out[OFF_VEL   + b + D3   ] = vp1 + vv1;
    out[OFF_VEL   + b + 2*D3 ] = vp2 + vv2;
}

// ---------------- BFECC advect passes ----------------
__global__ void advect_kernel(const float* __restrict__ ext_src, const float* __restrict__ tex,
                              const float* __restrict__ vel, float sgn, int mode) {
    int idx = blockIdx.x * blockDim.x + threadIdx.x;
    if (idx >= NB*D3) return;
    int p = idx % D3; int n = idx / D3;
    int k = p & 63, j = (p >> 6) & 63, i = p >> 12;

    float v0 = vel[(n*3    )*D3 + p];
    float v1 = vel[(n*3 + 1)*D3 + p];
    float v2 = vel[(n*3 + 2)*D3 + p];
    float px = (float)i - sgn*v2;
    float py = (float)j - sgn*v1;
    float pz = (float)k - sgn*v0;
    px = fminf(fmaxf(px, 0.f), 63.f);
    py = fminf(fmaxf(py, 0.f), 63.f);
    pz = fminf(fmaxf(pz, 0.f), 63.f);
    int x0 = (int)px; float fx = px - x0; int x1 = min(x0+1, 63);
    int y0 = (int)py; float fy = py - y0; int y1 = min(y0+1, 63);
    int z0 = (int)pz; float fz = pz - z0; int z1 = min(z0+1, 63);

    float w000 = (1-fx)*(1-fy)*(1-fz), w001 = (1-fx)*(1-fy)*fz;
    float w010 = (1-fx)*fy*(1-fz),     w011 = (1-fx)*fy*fz;
    float w100 = fx*(1-fy)*(1-fz),     w101 = fx*(1-fy)*fz;
    float w110 = fx*fy*(1-fz),         w111 = fx*fy*fz;

    int b00 = (x0*64 + y0)*64, b01 = (x0*64 + y1)*64;
    int b10 = (x1*64 + y0)*64, b11 = (x1*64 + y1)*64;

    const float* src = (mode == 0) ? ext_src : ((mode == 1) ? g_phi1 : g_comb);
    float* dst = (mode == 0) ? g_phi1 : ((mode == 1) ? g_comb : g_pred);

#pragma unroll
    for (int c = 0; c < 8; c++) {
        const float* s = src + (n*8 + c)*D3;
        float v = w000*s[b00+z0] + w001*s[b00+z1] + w010*s[b01+z0] + w011*s[b01+z1]
                + w100*s[b10+z0] + w101*s[b10+z1] + w110*s[b11+z0] + w111*s[b11+z1];
        if (mode == 1) v = 1.5f * tex[(n*8 + c)*D3 + p] - 0.5f * v;
        dst[(n*8 + c)*D3 + p] = v;
    }
}

// ---------------- LN + FF stage 1 (LN, @W1+b1, exact GELU) ----------------
__global__ void f1_kernel(const float* __restrict__ lng, const float* __restrict__ lnb,
                          const float* __restrict__ w1, const float* __restrict__ b1) {
    __shared__ float W[4096], Bv[64], G[64], Bt[64];
    for (int i = threadIdx.x; i < 4096; i += blockDim.x) W[i] = w1[i];
    if (threadIdx.x < 64) { Bv[threadIdx.x] = b1[threadIdx.x]; G[threadIdx.x] = lng[threadIdx.x]; Bt[threadIdx.x] = lnb[threadIdx.x]; }
    __syncthreads();

    int p = blockIdx.x * blockDim.x + threadIdx.x;
    if (p >= D3) return;
    float h[64]; float s = 0.f, s2 = 0.f;
#pragma unroll
    for (int c = 0; c < 64; c++) { float v = g_pred[c*D3 + p]; h[c] = v; s += v; s2 += v*v; }
    float mean = s * (1.f/64.f);
    float var  = s2 * (1.f/64.f) - mean*mean;
    float is = rsqrtf(var + 1e-5f);
#pragma unroll
    for (int c = 0; c < 64; c++) h[c] = (h[c] - mean) * is * G[c] + Bt[c];

    for (int jj = 0; jj < 64; jj++) {
        float a = Bv[jj];
#pragma unroll
        for (int ii = 0; ii < 64; ii++) a += h[ii] * W[ii*64 + jj];
        float g = 0.5f * a * (1.f + erff(a * 0.70710678118f));
        g_gbuf[jj*D3 + p] = g;
    }
}

// ---------------- FF stage 2 (@W2+b2, residual -> d_out x) ----------------
__global__ void f2_kernel(const float* __restrict__ w2, const float* __restrict__ b2,
                          float* __restrict__ out) {
    __shared__ float W[4096], Bv[64];
    for (int i = threadIdx.x; i < 4096; i += blockDim.x) W[i] = w2[i];
    if (threadIdx.x < 64) Bv[threadIdx.x] = b2[threadIdx.x];
    __syncthreads();

    int p = blockIdx.x * blockDim.x + threadIdx.x;
    if (p >= D3) return;
    float g[64];
#pragma unroll
    for (int c = 0; c < 64; c++) g[c] = g_gbuf[c*D3 + p];
    for (int jj = 0; jj < 64; jj++) {
        float a = Bv[jj];
#pragma unroll
        for (int ii = 0; ii < 64; ii++) a += g[ii] * W[ii*64 + jj];
        out[OFF_X + jj*D3 + p] = g_pred[jj*D3 + p] + a;
    }
}

// ---------------- host launch ----------------
extern "C" void kernel_launch(void* const* d_in, const int* in_sizes, int n_in,
                              void* d_out, int out_size) {
    const float* prev      = (const float*)d_in[0];
    const float* nxt       = (const float*)d_in[1];
    const float* texture   = (const float*)d_in[2];
    const float* mask      = (const float*)d_in[3];
    const float* boundary  = (const float*)d_in[4];
    const float* enc_w     = (const float*)d_in[5];
    const float* enc_b     = (const float*)d_in[6];
    const float* phi_c1_w  = (const float*)d_in[7];
    const float* phi_bn1_g = (const float*)d_in[8];
    const float* phi_bn1_b = (const float*)d_in[9];
    const float* phi_c2_w  = (const float*)d_in[10];
    const float* phi_bn2_g = (const float*)d_in[11];
    const float* phi_bn2_b = (const float*)d_in[12];
    const float* phi_out_w = (const float*)d_in[13];
    const float* phi_out_b = (const float*)d_in[14];
    const float* vort_c1_w = (const float*)d_in[15];
    const float* vort_bn1_g= (const float*)d_in[16];
    const float* vort_bn1_b= (const float*)d_in[17];
    const float* vort_c2_w = (const float*)d_in[18];
    const float* vort_bn2_g= (const float*)d_in[19];
    const float* vort_bn2_b= (const float*)d_in[20];
    const float* vort_out_w= (const float*)d_in[21];
    const float* vort_out_b= (const float*)d_in[22];
    const float* phi_weight= (const float*)d_in[23];
    const float* vort_weight=(const float*)d_in[24];
    const float* ln_g      = (const float*)d_in[25];
    const float* ln_b      = (const float*)d_in[26];
    const float* ff_w1     = (const float*)d_in[27];
    const float* ff_b1     = (const float*)d_in[28];
    const float* ff_w2     = (const float*)d_in[29];
    const float* ff_b2     = (const float*)d_in[30];
    float* out = (float*)d_out;

    pack_kernel<<<(3*WC1_PACK + 255)/256, 256>>>(phi_c1_w, vort_c1_w, phi_c2_w, vort_c2_w);

    int encBlocks = (NB*H3 + 255)/256;
    enc_kernel<<<encBlocks, 256>>>(prev, mask,     enc_w, enc_b, 0);
    enc_kernel<<<encBlocks, 256>>>(prev, boundary, enc_w, enc_b, 1);
    enc_kernel<<<encBlocks, 256>>>(nxt,  mask,     enc_w, enc_b, 2);

    corr_kernel<<<(NB*H3 + 255)/256, 256>>>();

    cudaFuncSetAttribute(conv1_kernel, cudaFuncAttributeMaxDynamicSharedMemorySize, 3*WC1_PACK*4);
    conv1_kernel<<<(NB*H3 + 255)/256, 256, 3*WC1_PACK*4>>>();

    bn_stats_partial<<<dim3(16, 32), 512>>>(0);
    bn_stats_final<<<16, 32>>>(0);

    int upN = NB*16*S3;
    upsample_kernel<<<(upN + 255)/256, 256>>>(phi_bn1_g, phi_bn1_b, vort_bn1_g, vort_bn1_b);

    conv2_kernel<<<(NB*S*S*33 + 255)/256, 256>>>();

    bn_stats_partial<<<dim3(16, 32), 512>>>(1);
    bn_stats_final<<<16, 32>>>(1);

    helm_kernel<<<(NB*S3 + 255)/256, 256>>>(phi_bn2_g, phi_bn2_b, vort_bn2_g, vort_bn2_b,
                                            phi_out_w, phi_out_b, vort_out_w, vort_out_b,
                                            phi_weight, vort_weight, out);

    vel_kernel<<<(NB*D3 + 255)/256, 256>>>(out);

    const float* vel = out + OFF_VEL;
    advect_kernel<<<(NB*D3 + 255)/256, 256>>>(texture, texture, vel,  1.f, 0);
    advect_kernel<<<(NB*D3 + 255)/256, 256>>>(texture, texture, vel, -1.f, 1);
    advect_kernel<<<(NB*D3 + 255)/256, 256>>>(texture, texture, vel,  1.f, 2);

    f1_kernel<<<(D3 + 127)/128, 128>>>(ln_g, ln_b, ff_w1, ff_b1);
    f2_kernel<<<(D3 + 127)/128, 128>>>(ff_w2, ff_b2, out);
}